// round 1
// baseline (speedup 1.0000x reference)
#include <cuda_runtime.h>

// MDTA: b=16, c=384, h=w=64, heads=8, d=48
#define Bn 16
#define Cn 384
#define Hn 64
#define Wn 64
#define HWn 4096
#define OCn 1152          // 3*C
#define NHn 8
#define DHn 48

// Scratch (device globals — allocation-free rule)
__device__ float g_qkv[(long)Bn*OCn*HWn];   // 1x1 conv output
__device__ float g_dw [(long)Bn*OCn*HWn];   // depthwise conv output (q,k,v)
__device__ float g_inv[2*Bn*Cn];            // inverse L2 norms for q,k channels
__device__ float g_attn[Bn*NHn*DHn*DHn];    // softmaxed attention
__device__ float g_P  [Bn*Cn*Cn];           // folded proj @ blockdiag(attn)

// ---------------------------------------------------------------------------
// SGEMM: C[m][n] = sum_k A[m][k] * B[k][n],  N fixed = 4096.
// A row-major MxK, B row-major KxN, C row-major MxN (stride 4096).
// BM=BN=128, BK=16, 256 threads, 8x8 per thread.
// ---------------------------------------------------------------------------
__global__ __launch_bounds__(256)
void sgemm_n4096(const float* __restrict__ A, long aStride,
                 const float* __restrict__ Bm, long bStride,
                 float* __restrict__ Cm, long cStride,
                 int M, int K)
{
    constexpr int BM = 128, BN = 128, BK = 16;
    __shared__ float As[BK][BM + 4];
    __shared__ float Bs[BK][BN + 4];

    const int bz = blockIdx.z;
    A  += aStride * bz;
    Bm += bStride * bz;
    Cm += cStride * bz;

    const int mBase = blockIdx.y * BM;
    const int nBase = blockIdx.x * BN;
    const int tid   = threadIdx.x;
    const int tx    = tid % 16;       // 16 col groups
    const int ty    = tid / 16;       // 16 row groups

    float acc[8][8];
#pragma unroll
    for (int i = 0; i < 8; i++)
#pragma unroll
        for (int j = 0; j < 8; j++) acc[i][j] = 0.f;

    for (int k0 = 0; k0 < K; k0 += BK) {
        // Load A tile (BMxBK) as float4 along K, store transposed
#pragma unroll
        for (int it = 0; it < 2; it++) {
            int idx = tid + it * 256;        // 0..511 float4
            int m   = idx >> 2;              // BK/4 = 4 float4 per row
            int kq  = idx & 3;
            float4 v = *reinterpret_cast<const float4*>(&A[(long)(mBase + m) * K + k0 + kq * 4]);
            As[kq * 4 + 0][m] = v.x;
            As[kq * 4 + 1][m] = v.y;
            As[kq * 4 + 2][m] = v.z;
            As[kq * 4 + 3][m] = v.w;
        }
        // Load B tile (BKxBN) as float4 along N
#pragma unroll
        for (int it = 0; it < 2; it++) {
            int idx = tid + it * 256;        // 0..511 float4
            int kr  = idx >> 5;              // BN/4 = 32 float4 per row
            int nq  = idx & 31;
            float4 v = *reinterpret_cast<const float4*>(&Bm[(long)(k0 + kr) * 4096 + nBase + nq * 4]);
            *reinterpret_cast<float4*>(&Bs[kr][nq * 4]) = v;
        }
        __syncthreads();

#pragma unroll
        for (int kk = 0; kk < BK; kk++) {
            float ar[8], br[8];
            float4 a0 = *reinterpret_cast<const float4*>(&As[kk][ty * 8]);
            float4 a1 = *reinterpret_cast<const float4*>(&As[kk][ty * 8 + 4]);
            float4 b0 = *reinterpret_cast<const float4*>(&Bs[kk][tx * 8]);
            float4 b1 = *reinterpret_cast<const float4*>(&Bs[kk][tx * 8 + 4]);
            ar[0]=a0.x; ar[1]=a0.y; ar[2]=a0.z; ar[3]=a0.w;
            ar[4]=a1.x; ar[5]=a1.y; ar[6]=a1.z; ar[7]=a1.w;
            br[0]=b0.x; br[1]=b0.y; br[2]=b0.z; br[3]=b0.w;
            br[4]=b1.x; br[5]=b1.y; br[6]=b1.z; br[7]=b1.w;
#pragma unroll
            for (int i = 0; i < 8; i++)
#pragma unroll
                for (int j = 0; j < 8; j++)
                    acc[i][j] += ar[i] * br[j];
        }
        __syncthreads();
    }

#pragma unroll
    for (int i = 0; i < 8; i++) {
        long m = mBase + ty * 8 + i;
        float4 v0 = make_float4(acc[i][0], acc[i][1], acc[i][2], acc[i][3]);
        float4 v1 = make_float4(acc[i][4], acc[i][5], acc[i][6], acc[i][7]);
        *reinterpret_cast<float4*>(&Cm[m * 4096 + nBase + tx * 8])     = v0;
        *reinterpret_cast<float4*>(&Cm[m * 4096 + nBase + tx * 8 + 4]) = v1;
    }
}

// ---------------------------------------------------------------------------
// Depthwise 3x3 SAME, zero pad. One block = 8 rows of one (b, ch) plane.
// ---------------------------------------------------------------------------
__global__ __launch_bounds__(512)
void dwconv3x3(const float* __restrict__ in, const float* __restrict__ wdw,
               float* __restrict__ out)
{
    __shared__ float sm[10][66];
    const int plane = blockIdx.y;            // b*OC + ch
    const int ch    = plane % OCn;
    const float* ip = in + (long)plane * HWn;

    float wgt[9];
#pragma unroll
    for (int t = 0; t < 9; t++) wgt[t] = wdw[ch * 9 + t];

    const int y0  = blockIdx.x * 8;
    const int tid = threadIdx.x;             // 512

    for (int idx = tid; idx < 10 * 66; idx += 512) {
        int ly = idx / 66, lx = idx % 66;
        int gy = y0 + ly - 1, gx = lx - 1;
        float v = 0.f;
        if (gy >= 0 && gy < Hn && gx >= 0 && gx < Wn) v = ip[gy * Wn + gx];
        sm[ly][lx] = v;
    }
    __syncthreads();

    const int tx = tid & 63, ty = tid >> 6;  // 64 x 8
    float s = 0.f;
#pragma unroll
    for (int ky = 0; ky < 3; ky++)
#pragma unroll
        for (int kx = 0; kx < 3; kx++)
            s += sm[ty + ky][tx + kx] * wgt[ky * 3 + kx];
    out[(long)plane * HWn + (y0 + ty) * Wn + tx] = s;
}

// ---------------------------------------------------------------------------
// Inverse L2 norms for q (which=0) and k (which=1) channels over hw.
// One block per (which,b,c). 256 threads.
// ---------------------------------------------------------------------------
__global__ __launch_bounds__(256)
void channel_invnorm(const float* __restrict__ dw, float* __restrict__ inv)
{
    const int idx   = blockIdx.x;            // 0 .. 2*B*C-1
    const int which = idx / (Bn * Cn);
    const int rem   = idx % (Bn * Cn);
    const int b     = rem / Cn;
    const int c     = rem % Cn;
    const float* p  = dw + ((long)b * OCn + which * Cn + c) * HWn;

    const int tid = threadIdx.x;
    float s = 0.f;
#pragma unroll
    for (int it = 0; it < 4; it++) {
        float4 v = *reinterpret_cast<const float4*>(&p[(tid + it * 256) * 4]);
        s += v.x * v.x + v.y * v.y + v.z * v.z + v.w * v.w;
    }
#pragma unroll
    for (int off = 16; off > 0; off >>= 1)
        s += __shfl_xor_sync(0xFFFFFFFFu, s, off);

    __shared__ float ws[8];
    if ((tid & 31) == 0) ws[tid >> 5] = s;
    __syncthreads();
    if (tid == 0) {
        float t = 0.f;
#pragma unroll
        for (int w = 0; w < 8; w++) t += ws[w];
        float n = sqrtf(t);
        inv[idx] = 1.f / fmaxf(n, 1e-12f);
    }
}

// ---------------------------------------------------------------------------
// Scores 48x48 per (b,h): G = q k^T, scale by invnorms * temperature,
// softmax rows, write attn. 256 threads (16x16, 3x3 micro-tile).
// ---------------------------------------------------------------------------
__global__ __launch_bounds__(256)
void scores_softmax(const float* __restrict__ dw, const float* __restrict__ inv,
                    const float* __restrict__ temp, float* __restrict__ attn)
{
    __shared__ float qs[DHn][68];
    __shared__ float ks[DHn][68];
    __shared__ float sc[DHn][DHn + 1];

    const int bh = blockIdx.x;
    const int b  = bh / NHn, h = bh % NHn;
    const float* qp = dw + ((long)b * OCn + h * DHn) * HWn;
    const float* kp = dw + ((long)b * OCn + Cn + h * DHn) * HWn;

    const int tid = threadIdx.x;
    const int tx  = tid % 16, ty = tid / 16;

    float acc[3][3] = {{0.f,0.f,0.f},{0.f,0.f,0.f},{0.f,0.f,0.f}};

    for (int k0 = 0; k0 < HWn; k0 += 64) {
        for (int i = tid; i < 48 * 16; i += 256) {
            int r = i / 16, cq = i % 16;
            *reinterpret_cast<float4*>(&qs[r][cq * 4]) =
                *reinterpret_cast<const float4*>(&qp[(long)r * HWn + k0 + cq * 4]);
            *reinterpret_cast<float4*>(&ks[r][cq * 4]) =
                *reinterpret_cast<const float4*>(&kp[(long)r * HWn + k0 + cq * 4]);
        }
        __syncthreads();
#pragma unroll 16
        for (int kk = 0; kk < 64; kk++) {
            float a0 = qs[ty * 3 + 0][kk], a1 = qs[ty * 3 + 1][kk], a2 = qs[ty * 3 + 2][kk];
            float b0 = ks[tx * 3 + 0][kk], b1 = ks[tx * 3 + 1][kk], b2 = ks[tx * 3 + 2][kk];
            acc[0][0] += a0 * b0; acc[0][1] += a0 * b1; acc[0][2] += a0 * b2;
            acc[1][0] += a1 * b0; acc[1][1] += a1 * b1; acc[1][2] += a1 * b2;
            acc[2][0] += a2 * b0; acc[2][1] += a2 * b1; acc[2][2] += a2 * b2;
        }
        __syncthreads();
    }

    const float tval = temp[h];
#pragma unroll
    for (int r = 0; r < 3; r++) {
        int i = ty * 3 + r;
        float iq = inv[b * Cn + h * DHn + i];
#pragma unroll
        for (int s = 0; s < 3; s++) {
            int j = tx * 3 + s;
            float ik = inv[Bn * Cn + b * Cn + h * DHn + j];
            sc[i][j] = acc[r][s] * iq * ik * tval;
        }
    }
    __syncthreads();

    if (tid < DHn) {
        float mx = -1e30f;
#pragma unroll
        for (int j = 0; j < DHn; j++) mx = fmaxf(mx, sc[tid][j]);
        float sum = 0.f;
#pragma unroll
        for (int j = 0; j < DHn; j++) {
            float e = expf(sc[tid][j] - mx);
            sc[tid][j] = e;
            sum += e;
        }
        float r = 1.f / sum;
        float* ap = attn + ((long)bh * DHn + tid) * DHn;
#pragma unroll
        for (int j = 0; j < DHn; j++) ap[j] = sc[tid][j] * r;
    }
}

// ---------------------------------------------------------------------------
// Fold: P[b][o][h*48+j] = sum_i w_proj[o][h*48+i] * attn[b,h,i,j]
// One block per (b,h), 384 threads (one per o).
// ---------------------------------------------------------------------------
__global__ __launch_bounds__(384)
void fold_proj(const float* __restrict__ wproj, const float* __restrict__ attn,
               float* __restrict__ P)
{
    __shared__ float at[DHn][DHn + 1];
    const int bh = blockIdx.x;
    const int b  = bh / NHn, h = bh % NHn;
    const int tid = threadIdx.x;

    for (int i = tid; i < DHn * DHn; i += 384)
        at[i / DHn][i % DHn] = attn[(long)bh * DHn * DHn + i];
    __syncthreads();

    const int o = tid;
    float wr[DHn];
#pragma unroll
    for (int i = 0; i < DHn; i++) wr[i] = wproj[o * Cn + h * DHn + i];

    float* pp = P + ((long)b * Cn + o) * Cn + h * DHn;
#pragma unroll 4
    for (int j = 0; j < DHn; j++) {
        float s = 0.f;
#pragma unroll
        for (int i = 0; i < DHn; i++) s += wr[i] * at[i][j];
        pp[j] = s;
    }
}

// ---------------------------------------------------------------------------
extern "C" void kernel_launch(void* const* d_in, const int* in_sizes, int n_in,
                              void* d_out, int out_size)
{
    const float* x     = (const float*)d_in[0];   // (16,384,64,64)
    const float* wqkv  = (const float*)d_in[1];   // (1152,384)
    const float* wdw   = (const float*)d_in[2];   // (1152,1,3,3)
    const float* wproj = (const float*)d_in[3];   // (384,384)
    const float* temp  = (const float*)d_in[4];   // (1,8,1,1)
    float* out = (float*)d_out;

    float *qkv, *dw, *inv, *attn, *P;
    cudaGetSymbolAddress((void**)&qkv,  g_qkv);
    cudaGetSymbolAddress((void**)&dw,   g_dw);
    cudaGetSymbolAddress((void**)&inv,  g_inv);
    cudaGetSymbolAddress((void**)&attn, g_attn);
    cudaGetSymbolAddress((void**)&P,    g_P);

    // K1: qkv = w_qkv @ x   (per batch: 1152x384 @ 384x4096)
    {
        dim3 grid(4096 / 128, OCn / 128, Bn);
        sgemm_n4096<<<grid, 256>>>(wqkv, 0, x, (long)Cn * HWn,
                                   qkv, (long)OCn * HWn, OCn, Cn);
    }
    // K2: depthwise 3x3
    {
        dim3 grid(Hn / 8, Bn * OCn);
        dwconv3x3<<<grid, 512>>>(qkv, wdw, dw);
    }
    // K3: inverse norms for q,k channels
    channel_invnorm<<<2 * Bn * Cn, 256>>>(dw, inv);

    // K4: scores + softmax
    scores_softmax<<<Bn * NHn, 256>>>(dw, inv, temp, attn);

    // K5: fold w_proj @ blockdiag(attn)
    fold_proj<<<Bn * NHn, 384>>>(wproj, attn, P);

    // K6: out = P @ v   (per batch: 384x384 @ 384x4096)
    {
        const float* v = dw + (long)2 * Cn * HWn;   // v channels start at 768
        dim3 grid(4096 / 128, Cn / 128, Bn);
        sgemm_n4096<<<grid, 256>>>(P, (long)Cn * Cn, v, (long)OCn * HWn,
                                   out, (long)Cn * HWn, Cn, Cn);
    }
}

// round 2
// speedup vs baseline: 1.9653x; 1.9653x over previous
#include <cuda_runtime.h>

// MDTA: b=16, c=384, h=w=64, heads=8, d=48
#define Bn 16
#define Cn 384
#define Hn 64
#define Wn 64
#define HWn 4096
#define OCn 1152          // 3*C
#define NHn 8
#define DHn 48
#define NCHUNK 8
#define CHSZ 512          // HW / NCHUNK

// Scratch (device globals — allocation-free rule)
__device__ float g_qkv [(long)Bn*OCn*HWn];      // 1x1 conv output
__device__ float g_dw  [(long)Bn*OCn*HWn];      // depthwise conv output (q,k,v)
__device__ float g_gram[(long)Bn*NHn*NCHUNK*DHn*DHn]; // partial Gram matrices
__device__ float g_nrm [(long)Bn*NHn*NCHUNK*2*DHn];   // partial sumsq (q then k)
__device__ float g_attn[Bn*NHn*DHn*DHn];        // softmaxed attention
__device__ float g_P   [Bn*Cn*Cn];              // folded proj @ blockdiag(attn)

__device__ __forceinline__ float f2tf32(float x) {
    unsigned u;
    asm("cvt.rna.tf32.f32 %0, %1;" : "=r"(u) : "f"(x));
    return __uint_as_float(u);
}

// ---------------------------------------------------------------------------
// tf32 tensor-core GEMM: C[m][n] = sum_k A[m][k]*B[k][n], N fixed = 4096.
// BM=BN=128, BK=16, 256 threads (8 warps as 2x4), warp tile 64x32,
// mma.sync.m16n8k8 tf32, fp32 accumulate. Double-buffered smem.
// M, K multiples of 128 / 16 (no predication needed here).
// ---------------------------------------------------------------------------
__global__ __launch_bounds__(256)
void gemm_tf32(const float* __restrict__ A, long aStride,
               const float* __restrict__ Bm, long bStride,
               float* __restrict__ Cm, long cStride,
               int K)
{
    constexpr int BM = 128, BN = 128, BK = 16;
    __shared__ float As[2][BM][BK + 4];
    __shared__ float Bs[2][BK][BN + 4];

    const int bz = blockIdx.z;
    A  += aStride * bz;
    Bm += bStride * bz;
    Cm += cStride * bz;

    const int mBase = blockIdx.y * BM;
    const int nBase = blockIdx.x * BN;
    const int tid   = threadIdx.x;
    const int lane  = tid & 31;
    const int w     = tid >> 5;
    const int warpM = w >> 2;          // 0..1
    const int warpN = w & 3;           // 0..3
    const int g     = lane >> 2;       // 0..7
    const int c     = lane & 3;        // 0..3

    float acc[4][4][4];
#pragma unroll
    for (int mt = 0; mt < 4; mt++)
#pragma unroll
        for (int nt = 0; nt < 4; nt++)
#pragma unroll
            for (int r = 0; r < 4; r++) acc[mt][nt][r] = 0.f;

    float4 aReg[2], bReg[2];

    auto loadG = [&](int k0) {
#pragma unroll
        for (int i = 0; i < 2; i++) {
            int idx = tid + i * 256;
            aReg[i] = *reinterpret_cast<const float4*>(
                &A[(long)(mBase + (idx >> 2)) * K + k0 + (idx & 3) * 4]);
            bReg[i] = *reinterpret_cast<const float4*>(
                &Bm[(long)(k0 + (idx >> 5)) * 4096 + nBase + (idx & 31) * 4]);
        }
    };
    auto stsT = [&](int s) {
#pragma unroll
        for (int i = 0; i < 2; i++) {
            int idx = tid + i * 256;
            int m = idx >> 2, kq = idx & 3;
            float4 va = aReg[i];
            float4 ca = make_float4(f2tf32(va.x), f2tf32(va.y), f2tf32(va.z), f2tf32(va.w));
            *reinterpret_cast<float4*>(&As[s][m][kq * 4]) = ca;
            int kr = idx >> 5, nq = idx & 31;
            float4 vb = bReg[i];
            float4 cb = make_float4(f2tf32(vb.x), f2tf32(vb.y), f2tf32(vb.z), f2tf32(vb.w));
            *reinterpret_cast<float4*>(&Bs[s][kr][nq * 4]) = cb;
        }
    };

    loadG(0);
    stsT(0);
    __syncthreads();

    const int nIter = K / BK;
    for (int it = 0; it < nIter; it++) {
        const int s = it & 1;
        if (it + 1 < nIter) loadG((it + 1) * BK);

        // compute on stage s
#pragma unroll
        for (int kk = 0; kk < BK; kk += 8) {
            unsigned af[4][4], bf[4][2];
#pragma unroll
            for (int mt = 0; mt < 4; mt++) {
                int row = warpM * 64 + mt * 16;
                af[mt][0] = __float_as_uint(As[s][row + g    ][kk + c    ]);
                af[mt][1] = __float_as_uint(As[s][row + g + 8][kk + c    ]);
                af[mt][2] = __float_as_uint(As[s][row + g    ][kk + c + 4]);
                af[mt][3] = __float_as_uint(As[s][row + g + 8][kk + c + 4]);
            }
#pragma unroll
            for (int nt = 0; nt < 4; nt++) {
                int col = warpN * 32 + nt * 8 + g;
                bf[nt][0] = __float_as_uint(Bs[s][kk + c    ][col]);
                bf[nt][1] = __float_as_uint(Bs[s][kk + c + 4][col]);
            }
#pragma unroll
            for (int mt = 0; mt < 4; mt++)
#pragma unroll
                for (int nt = 0; nt < 4; nt++) {
                    asm volatile(
                        "mma.sync.aligned.m16n8k8.row.col.f32.tf32.tf32.f32 "
                        "{%0,%1,%2,%3}, {%4,%5,%6,%7}, {%8,%9}, {%0,%1,%2,%3};"
                        : "+f"(acc[mt][nt][0]), "+f"(acc[mt][nt][1]),
                          "+f"(acc[mt][nt][2]), "+f"(acc[mt][nt][3])
                        : "r"(af[mt][0]), "r"(af[mt][1]), "r"(af[mt][2]), "r"(af[mt][3]),
                          "r"(bf[nt][0]), "r"(bf[nt][1]));
                }
        }

        if (it + 1 < nIter) stsT(s ^ 1);
        __syncthreads();
    }

    // epilogue
#pragma unroll
    for (int mt = 0; mt < 4; mt++) {
        long m0 = mBase + warpM * 64 + mt * 16 + g;
#pragma unroll
        for (int nt = 0; nt < 4; nt++) {
            int n0 = nBase + warpN * 32 + nt * 8 + c * 2;
            *reinterpret_cast<float2*>(&Cm[m0 * 4096 + n0]) =
                make_float2(acc[mt][nt][0], acc[mt][nt][1]);
            *reinterpret_cast<float2*>(&Cm[(m0 + 8) * 4096 + n0]) =
                make_float2(acc[mt][nt][2], acc[mt][nt][3]);
        }
    }
}

// ---------------------------------------------------------------------------
// Depthwise 3x3 SAME, zero pad. One block = 8 rows of one (b, ch) plane.
// ---------------------------------------------------------------------------
__global__ __launch_bounds__(512)
void dwconv3x3(const float* __restrict__ in, const float* __restrict__ wdw,
               float* __restrict__ out)
{
    __shared__ float sm[10][66];
    const int plane = blockIdx.y;            // b*OC + ch
    const int ch    = plane % OCn;
    const float* ip = in + (long)plane * HWn;

    float wgt[9];
#pragma unroll
    for (int t = 0; t < 9; t++) wgt[t] = wdw[ch * 9 + t];

    const int y0  = blockIdx.x * 8;
    const int tid = threadIdx.x;             // 512

    for (int idx = tid; idx < 10 * 66; idx += 512) {
        int ly = idx / 66, lx = idx % 66;
        int gy = y0 + ly - 1, gx = lx - 1;
        float v = 0.f;
        if (gy >= 0 && gy < Hn && gx >= 0 && gx < Wn) v = ip[gy * Wn + gx];
        sm[ly][lx] = v;
    }
    __syncthreads();

    const int tx = tid & 63, ty = tid >> 6;  // 64 x 8
    float s = 0.f;
#pragma unroll
    for (int ky = 0; ky < 3; ky++)
#pragma unroll
        for (int kx = 0; kx < 3; kx++)
            s += sm[ty + ky][tx + kx] * wgt[ky * 3 + kx];
    out[(long)plane * HWn + (y0 + ty) * Wn + tx] = s;
}

// ---------------------------------------------------------------------------
// Partial Gram + partial sum-of-squares over one hw chunk of 512.
// grid (NCHUNK, B*NH), block 256 (16x16, 3x3 micro-tile).
// ---------------------------------------------------------------------------
__global__ __launch_bounds__(256)
void gram_partial(const float* __restrict__ dw,
                  float* __restrict__ gram, float* __restrict__ nrm)
{
    __shared__ float qs[DHn][68];
    __shared__ float ks[DHn][68];

    const int chunk = blockIdx.x;
    const int bh    = blockIdx.y;
    const int b     = bh / NHn, h = bh % NHn;
    const float* qp = dw + ((long)b * OCn + h * DHn) * HWn + chunk * CHSZ;
    const float* kp = dw + ((long)b * OCn + Cn + h * DHn) * HWn + chunk * CHSZ;

    const int tid = threadIdx.x;
    const int tx  = tid % 16, ty = tid / 16;

    float acc[3][3] = {{0.f,0.f,0.f},{0.f,0.f,0.f},{0.f,0.f,0.f}};
    float sq[3] = {0.f,0.f,0.f};
    float sk[3] = {0.f,0.f,0.f};

    for (int k0 = 0; k0 < CHSZ; k0 += 64) {
        for (int i = tid; i < 48 * 16; i += 256) {
            int r = i / 16, cq = i % 16;
            *reinterpret_cast<float4*>(&qs[r][cq * 4]) =
                *reinterpret_cast<const float4*>(&qp[(long)r * HWn + k0 + cq * 4]);
            *reinterpret_cast<float4*>(&ks[r][cq * 4]) =
                *reinterpret_cast<const float4*>(&kp[(long)r * HWn + k0 + cq * 4]);
        }
        __syncthreads();
#pragma unroll 16
        for (int kk = 0; kk < 64; kk++) {
            float a0 = qs[ty * 3 + 0][kk], a1 = qs[ty * 3 + 1][kk], a2 = qs[ty * 3 + 2][kk];
            float b0 = ks[tx * 3 + 0][kk], b1 = ks[tx * 3 + 1][kk], b2 = ks[tx * 3 + 2][kk];
            acc[0][0] += a0 * b0; acc[0][1] += a0 * b1; acc[0][2] += a0 * b2;
            acc[1][0] += a1 * b0; acc[1][1] += a1 * b1; acc[1][2] += a1 * b2;
            acc[2][0] += a2 * b0; acc[2][1] += a2 * b1; acc[2][2] += a2 * b2;
            sq[0] += a0 * a0; sq[1] += a1 * a1; sq[2] += a2 * a2;
            sk[0] += b0 * b0; sk[1] += b1 * b1; sk[2] += b2 * b2;
        }
        __syncthreads();
    }

    float* gp = gram + ((long)bh * NCHUNK + chunk) * (DHn * DHn);
#pragma unroll
    for (int r = 0; r < 3; r++)
#pragma unroll
        for (int s = 0; s < 3; s++)
            gp[(ty * 3 + r) * DHn + tx * 3 + s] = acc[r][s];

    float* np = nrm + ((long)bh * NCHUNK + chunk) * (2 * DHn);
    if (tx == 0) {
#pragma unroll
        for (int r = 0; r < 3; r++) np[ty * 3 + r] = sq[r];
    }
    if (ty == 0) {
#pragma unroll
        for (int s = 0; s < 3; s++) np[DHn + tx * 3 + s] = sk[s];
    }
}

// ---------------------------------------------------------------------------
// Reduce chunks, scale by inv norms * temperature, softmax rows -> attn.
// grid B*NH, block 256.
// ---------------------------------------------------------------------------
__global__ __launch_bounds__(256)
void attn_final(const float* __restrict__ gram, const float* __restrict__ nrm,
                const float* __restrict__ temp, float* __restrict__ attn)
{
    __shared__ float sc[DHn][DHn + 1];
    __shared__ float invq[DHn], invk[DHn];

    const int bh = blockIdx.x;
    const int h  = bh % NHn;
    const int tid = threadIdx.x;

    if (tid < 2 * DHn) {
        float s = 0.f;
#pragma unroll
        for (int ch = 0; ch < NCHUNK; ch++)
            s += nrm[((long)bh * NCHUNK + ch) * (2 * DHn) + tid];
        float v = 1.f / fmaxf(sqrtf(s), 1e-12f);
        if (tid < DHn) invq[tid] = v; else invk[tid - DHn] = v;
    }
    __syncthreads();

    const float tval = temp[h];
    for (int i = tid; i < DHn * DHn; i += 256) {
        float s = 0.f;
#pragma unroll
        for (int ch = 0; ch < NCHUNK; ch++)
            s += gram[((long)bh * NCHUNK + ch) * (DHn * DHn) + i];
        int r = i / DHn, cc = i % DHn;
        sc[r][cc] = s * invq[r] * invk[cc] * tval;
    }
    __syncthreads();

    if (tid < DHn) {
        float mx = -1e30f;
#pragma unroll
        for (int j = 0; j < DHn; j++) mx = fmaxf(mx, sc[tid][j]);
        float sum = 0.f;
#pragma unroll
        for (int j = 0; j < DHn; j++) {
            float e = expf(sc[tid][j] - mx);
            sc[tid][j] = e;
            sum += e;
        }
        float r = 1.f / sum;
        float* ap = attn + ((long)bh * DHn + tid) * DHn;
#pragma unroll
        for (int j = 0; j < DHn; j++) ap[j] = sc[tid][j] * r;
    }
}

// ---------------------------------------------------------------------------
// Fold: P[b][o][h*48+j] = sum_i w_proj[o][h*48+i] * attn[b,h,i,j]
// ---------------------------------------------------------------------------
__global__ __launch_bounds__(384)
void fold_proj(const float* __restrict__ wproj, const float* __restrict__ attn,
               float* __restrict__ P)
{
    __shared__ float at[DHn][DHn + 1];
    const int bh = blockIdx.x;
    const int b  = bh / NHn, h = bh % NHn;
    const int tid = threadIdx.x;

    for (int i = tid; i < DHn * DHn; i += 384)
        at[i / DHn][i % DHn] = attn[(long)bh * DHn * DHn + i];
    __syncthreads();

    const int o = tid;
    float wr[DHn];
#pragma unroll
    for (int i = 0; i < DHn; i++) wr[i] = wproj[o * Cn + h * DHn + i];

    float* pp = P + ((long)b * Cn + o) * Cn + h * DHn;
#pragma unroll 4
    for (int j = 0; j < DHn; j++) {
        float s = 0.f;
#pragma unroll
        for (int i = 0; i < DHn; i++) s += wr[i] * at[i][j];
        pp[j] = s;
    }
}

// ---------------------------------------------------------------------------
extern "C" void kernel_launch(void* const* d_in, const int* in_sizes, int n_in,
                              void* d_out, int out_size)
{
    const float* x     = (const float*)d_in[0];   // (16,384,64,64)
    const float* wqkv  = (const float*)d_in[1];   // (1152,384)
    const float* wdw   = (const float*)d_in[2];   // (1152,1,3,3)
    const float* wproj = (const float*)d_in[3];   // (384,384)
    const float* temp  = (const float*)d_in[4];   // (1,8,1,1)
    float* out = (float*)d_out;

    float *qkv, *dw, *gram, *nrm, *attn, *P;
    cudaGetSymbolAddress((void**)&qkv,  g_qkv);
    cudaGetSymbolAddress((void**)&dw,   g_dw);
    cudaGetSymbolAddress((void**)&gram, g_gram);
    cudaGetSymbolAddress((void**)&nrm,  g_nrm);
    cudaGetSymbolAddress((void**)&attn, g_attn);
    cudaGetSymbolAddress((void**)&P,    g_P);

    // K1: qkv = w_qkv @ x  (per batch: 1152x384 @ 384x4096) — tf32 MMA
    {
        dim3 grid(4096 / 128, OCn / 128, Bn);
        gemm_tf32<<<grid, 256>>>(wqkv, 0, x, (long)Cn * HWn,
                                 qkv, (long)OCn * HWn, Cn);
    }
    // K2: depthwise 3x3
    {
        dim3 grid(Hn / 8, Bn * OCn);
        dwconv3x3<<<grid, 512>>>(qkv, wdw, dw);
    }
    // K3: partial Gram + sumsq over hw chunks
    {
        dim3 grid(NCHUNK, Bn * NHn);
        gram_partial<<<grid, 256>>>(dw, gram, nrm);
    }
    // K4: reduce + softmax
    attn_final<<<Bn * NHn, 256>>>(gram, nrm, temp, attn);

    // K5: fold w_proj @ blockdiag(attn)
    fold_proj<<<Bn * NHn, 384>>>(wproj, attn, P);

    // K6: out = P @ v  (per batch: 384x384 @ 384x4096) — tf32 MMA
    {
        const float* v = dw + (long)2 * Cn * HWn;
        dim3 grid(4096 / 128, Cn / 128, Bn);
        gemm_tf32<<<grid, 256>>>(P, (long)Cn * Cn, v, (long)OCn * HWn,
                                 out, (long)Cn * HWn, Cn);
    }
}